// round 11
// baseline (speedup 1.0000x reference)
#include <cuda_runtime.h>
#include <cuda_bf16.h>
#include <cstdint>
#include <math.h>

// Problem constants
#define SEQ   4096
#define NH    16
#define HD    64
#define DIM   1024
#define NQKV  3072
#define WIN_HALF 128
#define NGLOB 64

// ---------------------------------------------------------------------------
// Device-global scratch (allocation-free rule)
// ---------------------------------------------------------------------------
__device__ float g_Q[NH * SEQ * HD];               // [H][S][D] fp32
__device__ float g_K[NH * SEQ * HD];
__device__ float g_V[NH * SEQ * HD];
__device__ __nv_bfloat16 g_xh[SEQ * DIM];          // x split hi/lo [S][K]
__device__ __nv_bfloat16 g_xl[SEQ * DIM];
__device__ __nv_bfloat16 g_wqT_h[NQKV * DIM];      // w_qkv^T split [N][K]
__device__ __nv_bfloat16 g_wqT_l[NQKV * DIM];
__device__ __nv_bfloat16 g_woT_h[DIM * DIM];       // w_out^T split [N][K]
__device__ __nv_bfloat16 g_woT_l[DIM * DIM];
__device__ __nv_bfloat16 g_ah[SEQ * DIM];          // attn output split [S][H*D]
__device__ __nv_bfloat16 g_al[SEQ * DIM];

// ---------------------------------------------------------------------------
// Baseline-PTX helpers (sm_80+ baseline only; harness compiles at compute_103)
// ---------------------------------------------------------------------------
__device__ __forceinline__ uint32_t smem_to_u32(const void* smem_ptr) {
    uint32_t addr;
    asm("{ .reg .u64 tmp; cvta.to.shared.u64 tmp, %1; cvt.u32.u64 %0, tmp; }"
        : "=r"(addr) : "l"(smem_ptr));
    return addr;
}

__device__ __forceinline__ void cp_async16(uint32_t dst, const void* src) {
    asm volatile("cp.async.cg.shared.global [%0], [%1], 16;"
                 :: "r"(dst), "l"(src));
}
#define CP_ASYNC_COMMIT() asm volatile("cp.async.commit_group;" ::: "memory")
#define CP_ASYNC_WAIT_1() asm volatile("cp.async.wait_group 1;" ::: "memory")

__device__ __forceinline__ void ldsm_x4(uint32_t& r0, uint32_t& r1,
                                        uint32_t& r2, uint32_t& r3, uint32_t addr) {
    asm volatile("ldmatrix.sync.aligned.m8n8.x4.shared.b16 {%0,%1,%2,%3}, [%4];"
                 : "=r"(r0), "=r"(r1), "=r"(r2), "=r"(r3) : "r"(addr));
}

__device__ __forceinline__ void mma_bf16(float* c, const uint32_t* a, const uint32_t* b) {
    asm volatile(
        "mma.sync.aligned.m16n8k16.row.col.f32.bf16.bf16.f32 "
        "{%0,%1,%2,%3}, {%4,%5,%6,%7}, {%8,%9}, {%0,%1,%2,%3};"
        : "+f"(c[0]), "+f"(c[1]), "+f"(c[2]), "+f"(c[3])
        : "r"(a[0]), "r"(a[1]), "r"(a[2]), "r"(a[3]), "r"(b[0]), "r"(b[1]));
}

// ---------------------------------------------------------------------------
// bf16 split helper: v = hi + lo (each bf16), residual ~2^-16 * |v|
// ---------------------------------------------------------------------------
__device__ __forceinline__ void split_bf(float v, __nv_bfloat16& h, __nv_bfloat16& l) {
    h = __float2bfloat16(v);
    l = __float2bfloat16(v - __bfloat162float(h));
}

// ---------------------------------------------------------------------------
// Pre-pass 1: split x -> g_xh / g_xl
// ---------------------------------------------------------------------------
__global__ void conv_x_kernel(const float* __restrict__ x) {
    const int i = (blockIdx.x * blockDim.x + threadIdx.x) * 4;
    float4 v = *reinterpret_cast<const float4*>(x + i);
    __nv_bfloat16 h0, h1, h2, h3, l0, l1, l2, l3;
    split_bf(v.x, h0, l0); split_bf(v.y, h1, l1);
    split_bf(v.z, h2, l2); split_bf(v.w, h3, l3);
    g_xh[i + 0] = h0; g_xh[i + 1] = h1; g_xh[i + 2] = h2; g_xh[i + 3] = h3;
    g_xl[i + 0] = l0; g_xl[i + 1] = l1; g_xl[i + 2] = l2; g_xl[i + 3] = l3;
}

// ---------------------------------------------------------------------------
// Pre-pass 2: transpose + split W[K][N] -> [N][K] hi/lo
// ---------------------------------------------------------------------------
__global__ void tconv_wq_kernel(const float* __restrict__ W) {
    __shared__ float t[32][33];
    const int n0 = blockIdx.x * 32, k0 = blockIdx.y * 32;
    const int tx = threadIdx.x, ty = threadIdx.y;
#pragma unroll
    for (int i = 0; i < 32; i += 8)
        t[ty + i][tx] = W[(size_t)(k0 + ty + i) * NQKV + n0 + tx];
    __syncthreads();
#pragma unroll
    for (int i = 0; i < 32; i += 8) {
        float v = t[tx][ty + i];
        __nv_bfloat16 h, l; split_bf(v, h, l);
        g_wqT_h[(size_t)(n0 + ty + i) * DIM + k0 + tx] = h;
        g_wqT_l[(size_t)(n0 + ty + i) * DIM + k0 + tx] = l;
    }
}

__global__ void tconv_wo_kernel(const float* __restrict__ W) {
    __shared__ float t[32][33];
    const int n0 = blockIdx.x * 32, k0 = blockIdx.y * 32;
    const int tx = threadIdx.x, ty = threadIdx.y;
#pragma unroll
    for (int i = 0; i < 32; i += 8)
        t[ty + i][tx] = W[(size_t)(k0 + ty + i) * DIM + n0 + tx];
    __syncthreads();
#pragma unroll
    for (int i = 0; i < 32; i += 8) {
        float v = t[tx][ty + i];
        __nv_bfloat16 h, l; split_bf(v, h, l);
        g_woT_h[(size_t)(n0 + ty + i) * DIM + k0 + tx] = h;
        g_woT_l[(size_t)(n0 + ty + i) * DIM + k0 + tx] = l;
    }
}

// ---------------------------------------------------------------------------
// HMMA GEMM: C[M x N] = A[M x 1024] @ B^T (B stored [N][1024] bf16 hi/lo)
// Split-bf16 3-term, fp32 accumulate via mma.sync.m16n8k16.
// CTA tile 128x128, BK=32, 128 threads (4 warps, warp tile 64x64).
// TERM-MAJOR MMA ordering: 3 passes of 32 independent MMAs per ks-step so
// dependent accumulator reuse is ~32 issues apart (covers HMMA latency).
// cp.async double-buffered; 2 CTAs/SM. mode 0: scatter Q/K/V; 1: write Cout.
// ---------------------------------------------------------------------------
#define AP_BYTES   80        // padded row pitch (32 bf16 -> 40 elems = 80B)
#define T_TILE     10240     // one 128-row tile: 128 * 80
#define STAGE_B    40960     // 4 tiles (Ah, Al, Bh, Bl)
#define GEMM_SMEM  (2 * STAGE_B)

__global__ void __launch_bounds__(128) gemm_mma_kernel(float* __restrict__ Cout, int mode)
{
    extern __shared__ char smem_raw[];
    const uint32_t sb = smem_to_u32(smem_raw);

    const int tid  = threadIdx.x;
    const int wid  = tid >> 5;
    const int lane = tid & 31;
    const int wm   = wid & 1;        // 0..1  (M, 64 rows)
    const int wn   = wid >> 1;       // 0..1  (N, 64 cols)
    const int m0   = blockIdx.y * 128;
    const int n0   = blockIdx.x * 128;

    const __nv_bfloat16 *Ah, *Al, *Bh, *Bl;
    if (mode == 0) { Ah = g_xh; Al = g_xl; Bh = g_wqT_h; Bl = g_wqT_l; }
    else           { Ah = g_ah; Al = g_al; Bh = g_woT_h; Bl = g_woT_l; }

    // Loader: 2048 chunks of 16B per stage, 16 per thread.
    auto load_stage = [&](int stage, int kt) {
        const int k0 = kt * 32;
        const uint32_t sbase = sb + stage * STAGE_B;
#pragma unroll
        for (int e = 0; e < 16; e++) {
            const int cid  = e * 128 + tid;      // 0..2047
            const int tile = cid >> 9;           // 0:Ah 1:Al 2:Bh 3:Bl
            const int idx  = cid & 511;
            const int r    = idx >> 2;           // row 0..127
            const int ch   = idx & 3;            // 16B chunk
            const __nv_bfloat16* src;
            if (tile == 0)      src = Ah + (size_t)(m0 + r) * DIM + k0 + ch * 8;
            else if (tile == 1) src = Al + (size_t)(m0 + r) * DIM + k0 + ch * 8;
            else if (tile == 2) src = Bh + (size_t)(n0 + r) * DIM + k0 + ch * 8;
            else                src = Bl + (size_t)(n0 + r) * DIM + k0 + ch * 8;
            cp_async16(sbase + tile * T_TILE + r * AP_BYTES + ch * 16, src);
        }
    };

    const uint32_t a_off = (uint32_t)((wm * 64 + (lane & 15)) * AP_BYTES + (lane >> 4) * 16);
    const uint32_t b_off = (uint32_t)((wn * 64 + (lane & 15)) * AP_BYTES + (lane >> 4) * 16) + 2u * T_TILE;

    float acc[4][8][4];
#pragma unroll
    for (int i = 0; i < 4; i++)
#pragma unroll
        for (int j = 0; j < 8; j++)
#pragma unroll
            for (int e = 0; e < 4; e++) acc[i][j][e] = 0.0f;

    load_stage(0, 0); CP_ASYNC_COMMIT();
    load_stage(1, 1); CP_ASYNC_COMMIT();

    for (int kt = 0; kt < 32; kt++) {
        CP_ASYNC_WAIT_1();
        __syncthreads();
        const uint32_t sbase = sb + (uint32_t)(kt & 1) * STAGE_B;

#pragma unroll
        for (int ks = 0; ks < 2; ks++) {
            // Load ALL fragments for this ks-step up front
            uint32_t ah[4][4], al[4][4], bh[8][2], bl[8][2];
#pragma unroll
            for (int i = 0; i < 4; i++) {
                const uint32_t ad = sbase + a_off + i * (16 * AP_BYTES) + ks * 32;
                ldsm_x4(ah[i][0], ah[i][1], ah[i][2], ah[i][3], ad);
                ldsm_x4(al[i][0], al[i][1], al[i][2], al[i][3], ad + T_TILE);
            }
#pragma unroll
            for (int p = 0; p < 4; p++) {
                const uint32_t bd = sbase + b_off + p * (16 * AP_BYTES) + ks * 32;
                uint32_t t0, t1, t2, t3;
                ldsm_x4(t0, t1, t2, t3, bd);
                bh[2*p][0] = t0; bh[2*p][1] = t2; bh[2*p+1][0] = t1; bh[2*p+1][1] = t3;
                ldsm_x4(t0, t1, t2, t3, bd + T_TILE);
                bl[2*p][0] = t0; bl[2*p][1] = t2; bl[2*p+1][0] = t1; bl[2*p+1][1] = t3;
            }
            // Term-major: 3 passes of 32 independent MMAs
#pragma unroll
            for (int i = 0; i < 4; i++)
#pragma unroll
                for (int j = 0; j < 8; j++) mma_bf16(acc[i][j], ah[i], bh[j]);
#pragma unroll
            for (int i = 0; i < 4; i++)
#pragma unroll
                for (int j = 0; j < 8; j++) mma_bf16(acc[i][j], al[i], bh[j]);
#pragma unroll
            for (int i = 0; i < 4; i++)
#pragma unroll
                for (int j = 0; j < 8; j++) mma_bf16(acc[i][j], ah[i], bl[j]);
        }

        __syncthreads();
        if (kt + 2 < 32) load_stage(kt & 1, kt + 2);
        CP_ASYNC_COMMIT();
    }

    const int mbase = m0 + wm * 64 + (lane >> 2);
    const int nbase = n0 + wn * 64 + (lane & 3) * 2;
#pragma unroll
    for (int i = 0; i < 4; i++) {
        const int mlo = mbase + i * 16;
#pragma unroll
        for (int j = 0; j < 8; j++) {
            const int n = nbase + j * 8;
            if (mode == 0) {
                const int t = n >> 10, rem = n & 1023, h = rem >> 6, d = rem & 63;
                float* base = (t == 0 ? g_Q : (t == 1 ? g_K : g_V)) + (size_t)h * SEQ * HD + d;
                float2 v0; v0.x = acc[i][j][0]; v0.y = acc[i][j][1];
                float2 v1; v1.x = acc[i][j][2]; v1.y = acc[i][j][3];
                *reinterpret_cast<float2*>(base + (size_t)mlo * HD)       = v0;
                *reinterpret_cast<float2*>(base + (size_t)(mlo + 8) * HD) = v1;
            } else {
                float2 v0; v0.x = acc[i][j][0]; v0.y = acc[i][j][1];
                float2 v1; v1.x = acc[i][j][2]; v1.y = acc[i][j][3];
                *reinterpret_cast<float2*>(Cout + (size_t)mlo * DIM + n)       = v0;
                *reinterpret_cast<float2*>(Cout + (size_t)(mlo + 8) * DIM + n) = v1;
            }
        }
    }
}

// ---------------------------------------------------------------------------
// Attention: flash-style online softmax over <=4 key tiles of 64.
// fp32 math; float4 global loads; epilogue writes split bf16 into g_ah/g_al.
// ---------------------------------------------------------------------------
#define SP 65

__global__ void attn_kernel()
{
    extern __shared__ float sm[];
    float* Qs = sm;
    float* Ks = Qs + 64 * SP;
    float* Vs = Ks + 64 * SP;
    float* Ss = Vs + 64 * SP;

    const int h  = blockIdx.y;
    const int qt = blockIdx.x;
    const int qbase = qt * 64;

    const int tid = threadIdx.x;
    const int ty = tid >> 4;
    const int tx = tid & 15;

    const float* Qh = g_Q + (size_t)h * SEQ * HD;
    const float* Kh = g_K + (size_t)h * SEQ * HD;
    const float* Vh = g_V + (size_t)h * SEQ * HD;

#pragma unroll
    for (int e = 0; e < 4; e++) {
        const int idx = tid + e * 256;
        const int r = idx >> 4, c4 = (idx & 15) * 4;
        float4 v = *reinterpret_cast<const float4*>(Qh + (size_t)(qbase + r) * HD + c4);
        float* d = Qs + r * SP + c4;
        d[0] = v.x; d[1] = v.y; d[2] = v.z; d[3] = v.w;
    }

    float m_r[4], l_r[4], acc[4][4];
#pragma unroll
    for (int i = 0; i < 4; i++) {
        m_r[i] = -1e30f;
        l_r[i] = 0.0f;
#pragma unroll
        for (int j = 0; j < 4; j++) acc[i][j] = 0.0f;
    }

    int starts[4];
    int ns = 0;
    starts[ns++] = 0;
    if (qbase - 128 > 0) starts[ns++] = qbase - 128;
    if (qbase - 64  > 0) starts[ns++] = qbase - 64;
    if (qbase       > 0) starts[ns++] = qbase;

    const float scale = 0.125f;

    for (int it = 0; it < ns; it++) {
        const int kst = starts[it];
        __syncthreads();
#pragma unroll
        for (int e = 0; e < 4; e++) {
            const int idx = tid + e * 256;
            const int r = idx >> 4, c4 = (idx & 15) * 4;
            float4 kv = *reinterpret_cast<const float4*>(Kh + (size_t)(kst + r) * HD + c4);
            float4 vv = *reinterpret_cast<const float4*>(Vh + (size_t)(kst + r) * HD + c4);
            float* dk = Ks + r * SP + c4;
            float* dv = Vs + r * SP + c4;
            dk[0] = kv.x; dk[1] = kv.y; dk[2] = kv.z; dk[3] = kv.w;
            dv[0] = vv.x; dv[1] = vv.y; dv[2] = vv.z; dv[3] = vv.w;
        }
        __syncthreads();

        float sc[4][4];
#pragma unroll
        for (int i = 0; i < 4; i++)
#pragma unroll
            for (int j = 0; j < 4; j++) sc[i][j] = 0.0f;

#pragma unroll 8
        for (int d = 0; d < 64; d++) {
            float a[4], b[4];
#pragma unroll
            for (int i = 0; i < 4; i++) a[i] = Qs[(ty * 4 + i) * SP + d];
#pragma unroll
            for (int j = 0; j < 4; j++) b[j] = Ks[(tx * 4 + j) * SP + d];
#pragma unroll
            for (int i = 0; i < 4; i++)
#pragma unroll
                for (int j = 0; j < 4; j++) sc[i][j] = fmaf(a[i], b[j], sc[i][j]);
        }

        float tmax[4];
#pragma unroll
        for (int i = 0; i < 4; i++) {
            const int iq = qbase + ty * 4 + i;
            float mx = -1e30f;
#pragma unroll
            for (int j = 0; j < 4; j++) {
                const int jk = kst + tx * 4 + j;
                const bool valid = (jk <= iq) && ((jk >= iq - WIN_HALF) || (jk < NGLOB));
                const float v = valid ? sc[i][j] * scale : -1e30f;
                sc[i][j] = v;
                mx = fmaxf(mx, v);
            }
            tmax[i] = mx;
        }

#pragma unroll
        for (int off = 1; off < 16; off <<= 1)
#pragma unroll
            for (int i = 0; i < 4; i++)
                tmax[i] = fmaxf(tmax[i], __shfl_xor_sync(0xffffffffu, tmax[i], off));

        float psum[4];
#pragma unroll
        for (int i = 0; i < 4; i++) {
            const float mnew = fmaxf(m_r[i], tmax[i]);
            const float alpha = __expf(m_r[i] - mnew);
            m_r[i] = mnew;
            float ps = 0.0f;
#pragma unroll
            for (int j = 0; j < 4; j++) {
                const float p = __expf(sc[i][j] - mnew);
                sc[i][j] = p;
                ps += p;
            }
            psum[i] = ps;
            l_r[i] *= alpha;
#pragma unroll
            for (int j = 0; j < 4; j++) acc[i][j] *= alpha;
        }
#pragma unroll
        for (int off = 1; off < 16; off <<= 1)
#pragma unroll
            for (int i = 0; i < 4; i++)
                psum[i] += __shfl_xor_sync(0xffffffffu, psum[i], off);
#pragma unroll
        for (int i = 0; i < 4; i++) l_r[i] += psum[i];

#pragma unroll
        for (int i = 0; i < 4; i++)
#pragma unroll
            for (int j = 0; j < 4; j++)
                Ss[(ty * 4 + i) * SP + tx * 4 + j] = sc[i][j];
        __syncthreads();

#pragma unroll 8
        for (int c = 0; c < 64; c++) {
            float a[4], b[4];
#pragma unroll
            for (int j = 0; j < 4; j++) b[j] = Vs[c * SP + tx * 4 + j];
#pragma unroll
            for (int i = 0; i < 4; i++) a[i] = Ss[(ty * 4 + i) * SP + c];
#pragma unroll
            for (int i = 0; i < 4; i++)
#pragma unroll
                for (int j = 0; j < 4; j++) acc[i][j] = fmaf(a[i], b[j], acc[i][j]);
        }
    }

    // Normalize + split-store to g_ah/g_al [S][H*D]
#pragma unroll
    for (int i = 0; i < 4; i++) {
        const int s = qbase + ty * 4 + i;
        const float inv = 1.0f / l_r[i];
#pragma unroll
        for (int j = 0; j < 4; j++) {
            const float o = acc[i][j] * inv;
            __nv_bfloat16 hh, ll; split_bf(o, hh, ll);
            const size_t oi = (size_t)s * DIM + h * HD + tx * 4 + j;
            g_ah[oi] = hh;
            g_al[oi] = ll;
        }
    }
}

// ---------------------------------------------------------------------------
// Launcher
// ---------------------------------------------------------------------------
extern "C" void kernel_launch(void* const* d_in, const int* in_sizes, int n_in,
                              void* d_out, int out_size)
{
    const float* x     = (const float*)d_in[0];   // [1,4096,1024]
    const float* w_qkv = (const float*)d_in[1];   // [1024,3072]
    const float* w_out = (const float*)d_in[2];   // [1024,1024]
    float* out = (float*)d_out;                   // [1,4096,1024]

    // Pre-pass: split/transpose inputs to bf16 hi/lo
    conv_x_kernel<<<SEQ * DIM / 4 / 256, 256>>>(x);
    tconv_wq_kernel<<<dim3(NQKV / 32, DIM / 32), dim3(32, 8)>>>(w_qkv);
    tconv_wo_kernel<<<dim3(DIM / 32, DIM / 32), dim3(32, 8)>>>(w_out);

    // 1) QKV projection (HMMA, scatter into g_Q/g_K/g_V)
    cudaFuncSetAttribute(gemm_mma_kernel, cudaFuncAttributeMaxDynamicSharedMemorySize, GEMM_SMEM);
    gemm_mma_kernel<<<dim3(NQKV / 128, SEQ / 128), 128, GEMM_SMEM>>>(nullptr, 0);

    // 2) Sparse attention (fp32, writes split-bf16 attn output)
    const int attn_smem = 4 * 64 * SP * (int)sizeof(float);
    cudaFuncSetAttribute(attn_kernel, cudaFuncAttributeMaxDynamicSharedMemorySize, attn_smem);
    attn_kernel<<<dim3(SEQ / 64, NH), 256, attn_smem>>>();

    // 3) Output projection (HMMA)
    gemm_mma_kernel<<<dim3(DIM / 128, SEQ / 128), 128, GEMM_SMEM>>>(out, 1);
}

// round 13
// speedup vs baseline: 1.1873x; 1.1873x over previous
#include <cuda_runtime.h>
#include <cuda_fp16.h>
#include <cstdint>
#include <math.h>

// Problem constants
#define SEQ   4096
#define NH    16
#define HD    64
#define DIM   1024
#define NQKV  3072
#define WIN_HALF 128
#define NGLOB 64

// ---------------------------------------------------------------------------
// Device-global scratch (allocation-free rule)
// ---------------------------------------------------------------------------
__device__ float g_Q[NH * SEQ * HD];               // [H][S][D] fp32
__device__ float g_K[NH * SEQ * HD];
__device__ float g_V[NH * SEQ * HD];
__device__ __half g_xh[SEQ * DIM];                 // x split hi/lo fp16 [S][K]
__device__ __half g_xl[SEQ * DIM];
__device__ __half g_wqT[NQKV * DIM];               // w_qkv^T fp16 [N][K]
__device__ __half g_woT[DIM * DIM];                // w_out^T fp16 [N][K]
__device__ __half g_ah[SEQ * DIM];                 // attn out split fp16 [S][H*D]
__device__ __half g_al[SEQ * DIM];

// ---------------------------------------------------------------------------
// Baseline-PTX helpers (sm_80+ baseline only; harness compiles at compute_103)
// ---------------------------------------------------------------------------
__device__ __forceinline__ uint32_t smem_to_u32(const void* smem_ptr) {
    uint32_t addr;
    asm("{ .reg .u64 tmp; cvta.to.shared.u64 tmp, %1; cvt.u32.u64 %0, tmp; }"
        : "=r"(addr) : "l"(smem_ptr));
    return addr;
}

__device__ __forceinline__ void cp_async16(uint32_t dst, const void* src) {
    asm volatile("cp.async.cg.shared.global [%0], [%1], 16;"
                 :: "r"(dst), "l"(src));
}
#define CP_ASYNC_COMMIT() asm volatile("cp.async.commit_group;" ::: "memory")
#define CP_ASYNC_WAIT_2() asm volatile("cp.async.wait_group 2;" ::: "memory")

__device__ __forceinline__ void ldsm_x4(uint32_t& r0, uint32_t& r1,
                                        uint32_t& r2, uint32_t& r3, uint32_t addr) {
    asm volatile("ldmatrix.sync.aligned.m8n8.x4.shared.b16 {%0,%1,%2,%3}, [%4];"
                 : "=r"(r0), "=r"(r1), "=r"(r2), "=r"(r3) : "r"(addr));
}

__device__ __forceinline__ void mma_f16(float* c, const uint32_t* a, const uint32_t* b) {
    asm volatile(
        "mma.sync.aligned.m16n8k16.row.col.f32.f16.f16.f32 "
        "{%0,%1,%2,%3}, {%4,%5,%6,%7}, {%8,%9}, {%0,%1,%2,%3};"
        : "+f"(c[0]), "+f"(c[1]), "+f"(c[2]), "+f"(c[3])
        : "r"(a[0]), "r"(a[1]), "r"(a[2]), "r"(a[3]), "r"(b[0]), "r"(b[1]));
}

// ---------------------------------------------------------------------------
// fp16 split: v = hi + lo (each fp16) -> ~22-bit effective mantissa
// ---------------------------------------------------------------------------
__device__ __forceinline__ void split_h(float v, __half& h, __half& l) {
    h = __float2half_rn(v);
    l = __float2half_rn(v - __half2float(h));
}

// ---------------------------------------------------------------------------
// Pre-pass 1: split x -> g_xh / g_xl (fp16 hi/lo)
// ---------------------------------------------------------------------------
__global__ void conv_x_kernel(const float* __restrict__ x) {
    const int i = (blockIdx.x * blockDim.x + threadIdx.x) * 4;
    float4 v = *reinterpret_cast<const float4*>(x + i);
    __half h0, h1, h2, h3, l0, l1, l2, l3;
    split_h(v.x, h0, l0); split_h(v.y, h1, l1);
    split_h(v.z, h2, l2); split_h(v.w, h3, l3);
    g_xh[i + 0] = h0; g_xh[i + 1] = h1; g_xh[i + 2] = h2; g_xh[i + 3] = h3;
    g_xl[i + 0] = l0; g_xl[i + 1] = l1; g_xl[i + 2] = l2; g_xl[i + 3] = l3;
}

// ---------------------------------------------------------------------------
// Pre-pass 2: transpose W[K][N] -> [N][K] fp16 (round-to-nearest)
// ---------------------------------------------------------------------------
__global__ void tconv_wq_kernel(const float* __restrict__ W) {
    __shared__ float t[32][33];
    const int n0 = blockIdx.x * 32, k0 = blockIdx.y * 32;
    const int tx = threadIdx.x, ty = threadIdx.y;
#pragma unroll
    for (int i = 0; i < 32; i += 8)
        t[ty + i][tx] = W[(size_t)(k0 + ty + i) * NQKV + n0 + tx];
    __syncthreads();
#pragma unroll
    for (int i = 0; i < 32; i += 8)
        g_wqT[(size_t)(n0 + ty + i) * DIM + k0 + tx] = __float2half_rn(t[tx][ty + i]);
}

__global__ void tconv_wo_kernel(const float* __restrict__ W) {
    __shared__ float t[32][33];
    const int n0 = blockIdx.x * 32, k0 = blockIdx.y * 32;
    const int tx = threadIdx.x, ty = threadIdx.y;
#pragma unroll
    for (int i = 0; i < 32; i += 8)
        t[ty + i][tx] = W[(size_t)(k0 + ty + i) * DIM + n0 + tx];
    __syncthreads();
#pragma unroll
    for (int i = 0; i < 32; i += 8)
        g_woT[(size_t)(n0 + ty + i) * DIM + k0 + tx] = __float2half_rn(t[tx][ty + i]);
}

// ---------------------------------------------------------------------------
// HMMA GEMM: C[M x N] = A[M x 1024] @ B^T (B stored [N][1024] fp16)
// fp16 A-split 2-term: C = Ah*Bh + Al*Bh, fp32 accumulate, m16n8k16.
// CTA tile 128x128, BK=32, 128 threads (4 warps, warp tile 64x64).
// cp.async 3-stage pipeline; 2 CTAs/SM. mode 0: scatter Q/K/V; 1: write Cout.
// ---------------------------------------------------------------------------
#define AP_BYTES   80        // padded row pitch (32 fp16 -> 40 elems = 80B)
#define T_TILE     10240     // one 128-row tile: 128 * 80
#define STAGE_B    30720     // 3 tiles (Ah, Al, Bh)
#define N_STAGE    3
#define GEMM_SMEM  (N_STAGE * STAGE_B)

__global__ void __launch_bounds__(128) gemm_mma_kernel(float* __restrict__ Cout, int mode)
{
    extern __shared__ char smem_raw[];
    const uint32_t sb = smem_to_u32(smem_raw);

    const int tid  = threadIdx.x;
    const int wid  = tid >> 5;
    const int lane = tid & 31;
    const int wm   = wid & 1;        // 0..1  (M, 64 rows)
    const int wn   = wid >> 1;       // 0..1  (N, 64 cols)
    const int m0   = blockIdx.y * 128;
    const int n0   = blockIdx.x * 128;

    const __half *Ah, *Al, *Bh;
    if (mode == 0) { Ah = g_xh; Al = g_xl; Bh = g_wqT; }
    else           { Ah = g_ah; Al = g_al; Bh = g_woT; }

    // Loader: 1536 chunks of 16B per stage, 12 per thread.
    auto load_stage = [&](int stage, int kt) {
        const int k0 = kt * 32;
        const uint32_t sbase = sb + stage * STAGE_B;
#pragma unroll
        for (int e = 0; e < 12; e++) {
            const int cid  = e * 128 + tid;      // 0..1535
            const int tile = cid >> 9;           // 0:Ah 1:Al 2:Bh
            const int idx  = cid & 511;
            const int r    = idx >> 2;           // row 0..127
            const int ch   = idx & 3;            // 16B chunk
            const __half* src;
            if (tile == 0)      src = Ah + (size_t)(m0 + r) * DIM + k0 + ch * 8;
            else if (tile == 1) src = Al + (size_t)(m0 + r) * DIM + k0 + ch * 8;
            else                src = Bh + (size_t)(n0 + r) * DIM + k0 + ch * 8;
            cp_async16(sbase + tile * T_TILE + r * AP_BYTES + ch * 16, src);
        }
    };

    const uint32_t a_off = (uint32_t)((wm * 64 + (lane & 15)) * AP_BYTES + (lane >> 4) * 16);
    const uint32_t b_off = (uint32_t)((wn * 64 + (lane & 15)) * AP_BYTES + (lane >> 4) * 16) + 2u * T_TILE;

    float acc[4][8][4];
#pragma unroll
    for (int i = 0; i < 4; i++)
#pragma unroll
        for (int j = 0; j < 8; j++)
#pragma unroll
            for (int e = 0; e < 4; e++) acc[i][j][e] = 0.0f;

    load_stage(0, 0); CP_ASYNC_COMMIT();
    load_stage(1, 1); CP_ASYNC_COMMIT();
    load_stage(2, 2); CP_ASYNC_COMMIT();

    int stg = 0;
    for (int kt = 0; kt < 32; kt++) {
        CP_ASYNC_WAIT_2();
        __syncthreads();
        const uint32_t sbase = sb + (uint32_t)stg * STAGE_B;

#pragma unroll
        for (int ks = 0; ks < 2; ks++) {
            uint32_t ah[4][4], al[4][4], bh[8][2];
#pragma unroll
            for (int i = 0; i < 4; i++) {
                const uint32_t ad = sbase + a_off + i * (16 * AP_BYTES) + ks * 32;
                ldsm_x4(ah[i][0], ah[i][1], ah[i][2], ah[i][3], ad);
                ldsm_x4(al[i][0], al[i][1], al[i][2], al[i][3], ad + T_TILE);
            }
#pragma unroll
            for (int p = 0; p < 4; p++) {
                const uint32_t bd = sbase + b_off + p * (16 * AP_BYTES) + ks * 32;
                uint32_t t0, t1, t2, t3;
                ldsm_x4(t0, t1, t2, t3, bd);
                bh[2*p][0] = t0; bh[2*p][1] = t2; bh[2*p+1][0] = t1; bh[2*p+1][1] = t3;
            }
            // Two passes of 32 independent MMAs
#pragma unroll
            for (int i = 0; i < 4; i++)
#pragma unroll
                for (int j = 0; j < 8; j++) mma_f16(acc[i][j], ah[i], bh[j]);
#pragma unroll
            for (int i = 0; i < 4; i++)
#pragma unroll
                for (int j = 0; j < 8; j++) mma_f16(acc[i][j], al[i], bh[j]);
        }

        __syncthreads();
        if (kt + 3 < 32) load_stage(stg, kt + 3);
        CP_ASYNC_COMMIT();
        stg = (stg == N_STAGE - 1) ? 0 : stg + 1;
    }

    const int mbase = m0 + wm * 64 + (lane >> 2);
    const int nbase = n0 + wn * 64 + (lane & 3) * 2;
#pragma unroll
    for (int i = 0; i < 4; i++) {
        const int mlo = mbase + i * 16;
#pragma unroll
        for (int j = 0; j < 8; j++) {
            const int n = nbase + j * 8;
            if (mode == 0) {
                const int t = n >> 10, rem = n & 1023, h = rem >> 6, d = rem & 63;
                float* base = (t == 0 ? g_Q : (t == 1 ? g_K : g_V)) + (size_t)h * SEQ * HD + d;
                float2 v0; v0.x = acc[i][j][0]; v0.y = acc[i][j][1];
                float2 v1; v1.x = acc[i][j][2]; v1.y = acc[i][j][3];
                *reinterpret_cast<float2*>(base + (size_t)mlo * HD)       = v0;
                *reinterpret_cast<float2*>(base + (size_t)(mlo + 8) * HD) = v1;
            } else {
                float2 v0; v0.x = acc[i][j][0]; v0.y = acc[i][j][1];
                float2 v1; v1.x = acc[i][j][2]; v1.y = acc[i][j][3];
                *reinterpret_cast<float2*>(Cout + (size_t)mlo * DIM + n)       = v0;
                *reinterpret_cast<float2*>(Cout + (size_t)(mlo + 8) * DIM + n) = v1;
            }
        }
    }
}

// ---------------------------------------------------------------------------
// Attention: flash-style online softmax over <=4 key tiles of 64.
// fp32 math; float4 global loads; epilogue writes split fp16 into g_ah/g_al.
// ---------------------------------------------------------------------------
#define SP 65

__global__ void attn_kernel()
{
    extern __shared__ float sm[];
    float* Qs = sm;
    float* Ks = Qs + 64 * SP;
    float* Vs = Ks + 64 * SP;
    float* Ss = Vs + 64 * SP;

    const int h  = blockIdx.y;
    const int qt = blockIdx.x;
    const int qbase = qt * 64;

    const int tid = threadIdx.x;
    const int ty = tid >> 4;
    const int tx = tid & 15;

    const float* Qh = g_Q + (size_t)h * SEQ * HD;
    const float* Kh = g_K + (size_t)h * SEQ * HD;
    const float* Vh = g_V + (size_t)h * SEQ * HD;

#pragma unroll
    for (int e = 0; e < 4; e++) {
        const int idx = tid + e * 256;
        const int r = idx >> 4, c4 = (idx & 15) * 4;
        float4 v = *reinterpret_cast<const float4*>(Qh + (size_t)(qbase + r) * HD + c4);
        float* d = Qs + r * SP + c4;
        d[0] = v.x; d[1] = v.y; d[2] = v.z; d[3] = v.w;
    }

    float m_r[4], l_r[4], acc[4][4];
#pragma unroll
    for (int i = 0; i < 4; i++) {
        m_r[i] = -1e30f;
        l_r[i] = 0.0f;
#pragma unroll
        for (int j = 0; j < 4; j++) acc[i][j] = 0.0f;
    }

    int starts[4];
    int ns = 0;
    starts[ns++] = 0;
    if (qbase - 128 > 0) starts[ns++] = qbase - 128;
    if (qbase - 64  > 0) starts[ns++] = qbase - 64;
    if (qbase       > 0) starts[ns++] = qbase;

    const float scale = 0.125f;

    for (int it = 0; it < ns; it++) {
        const int kst = starts[it];
        __syncthreads();
#pragma unroll
        for (int e = 0; e < 4; e++) {
            const int idx = tid + e * 256;
            const int r = idx >> 4, c4 = (idx & 15) * 4;
            float4 kv = *reinterpret_cast<const float4*>(Kh + (size_t)(kst + r) * HD + c4);
            float4 vv = *reinterpret_cast<const float4*>(Vh + (size_t)(kst + r) * HD + c4);
            float* dk = Ks + r * SP + c4;
            float* dv = Vs + r * SP + c4;
            dk[0] = kv.x; dk[1] = kv.y; dk[2] = kv.z; dk[3] = kv.w;
            dv[0] = vv.x; dv[1] = vv.y; dv[2] = vv.z; dv[3] = vv.w;
        }
        __syncthreads();

        float sc[4][4];
#pragma unroll
        for (int i = 0; i < 4; i++)
#pragma unroll
            for (int j = 0; j < 4; j++) sc[i][j] = 0.0f;

#pragma unroll 8
        for (int d = 0; d < 64; d++) {
            float a[4], b[4];
#pragma unroll
            for (int i = 0; i < 4; i++) a[i] = Qs[(ty * 4 + i) * SP + d];
#pragma unroll
            for (int j = 0; j < 4; j++) b[j] = Ks[(tx * 4 + j) * SP + d];
#pragma unroll
            for (int i = 0; i < 4; i++)
#pragma unroll
                for (int j = 0; j < 4; j++) sc[i][j] = fmaf(a[i], b[j], sc[i][j]);
        }

        float tmax[4];
#pragma unroll
        for (int i = 0; i < 4; i++) {
            const int iq = qbase + ty * 4 + i;
            float mx = -1e30f;
#pragma unroll
            for (int j = 0; j < 4; j++) {
                const int jk = kst + tx * 4 + j;
                const bool valid = (jk <= iq) && ((jk >= iq - WIN_HALF) || (jk < NGLOB));
                const float v = valid ? sc[i][j] * scale : -1e30f;
                sc[i][j] = v;
                mx = fmaxf(mx, v);
            }
            tmax[i] = mx;
        }

#pragma unroll
        for (int off = 1; off < 16; off <<= 1)
#pragma unroll
            for (int i = 0; i < 4; i++)
                tmax[i] = fmaxf(tmax[i], __shfl_xor_sync(0xffffffffu, tmax[i], off));

        float psum[4];
#pragma unroll
        for (int i = 0; i < 4; i++) {
            const float mnew = fmaxf(m_r[i], tmax[i]);
            const float alpha = __expf(m_r[i] - mnew);
            m_r[i] = mnew;
            float ps = 0.0f;
#pragma unroll
            for (int j = 0; j < 4; j++) {
                const float p = __expf(sc[i][j] - mnew);
                sc[i][j] = p;
                ps += p;
            }
            psum[i] = ps;
            l_r[i] *= alpha;
#pragma unroll
            for (int j = 0; j < 4; j++) acc[i][j] *= alpha;
        }
#pragma unroll
        for (int off = 1; off < 16; off <<= 1)
#pragma unroll
            for (int i = 0; i < 4; i++)
                psum[i] += __shfl_xor_sync(0xffffffffu, psum[i], off);
#pragma unroll
        for (int i = 0; i < 4; i++) l_r[i] += psum[i];

#pragma unroll
        for (int i = 0; i < 4; i++)
#pragma unroll
            for (int j = 0; j < 4; j++)
                Ss[(ty * 4 + i) * SP + tx * 4 + j] = sc[i][j];
        __syncthreads();

#pragma unroll 8
        for (int c = 0; c < 64; c++) {
            float a[4], b[4];
#pragma unroll
            for (int j = 0; j < 4; j++) b[j] = Vs[c * SP + tx * 4 + j];
#pragma unroll
            for (int i = 0; i < 4; i++) a[i] = Ss[(ty * 4 + i) * SP + c];
#pragma unroll
            for (int i = 0; i < 4; i++)
#pragma unroll
                for (int j = 0; j < 4; j++) acc[i][j] = fmaf(a[i], b[j], acc[i][j]);
        }
    }

    // Normalize + split-store to g_ah/g_al [S][H*D] (fp16 hi/lo)
#pragma unroll
    for (int i = 0; i < 4; i++) {
        const int s = qbase + ty * 4 + i;
        const float inv = 1.0f / l_r[i];
#pragma unroll
        for (int j = 0; j < 4; j++) {
            const float o = acc[i][j] * inv;
            __half hh, ll; split_h(o, hh, ll);
            const size_t oi = (size_t)s * DIM + h * HD + tx * 4 + j;
            g_ah[oi] = hh;
            g_al[oi] = ll;
        }
    }
}

// ---------------------------------------------------------------------------
// Launcher
// ---------------------------------------------------------------------------
extern "C" void kernel_launch(void* const* d_in, const int* in_sizes, int n_in,
                              void* d_out, int out_size)
{
    const float* x     = (const float*)d_in[0];   // [1,4096,1024]
    const float* w_qkv = (const float*)d_in[1];   // [1024,3072]
    const float* w_out = (const float*)d_in[2];   // [1024,1024]
    float* out = (float*)d_out;                   // [1,4096,1024]

    // Pre-pass: split x to fp16 hi/lo; transpose+round weights to fp16
    conv_x_kernel<<<SEQ * DIM / 4 / 256, 256>>>(x);
    tconv_wq_kernel<<<dim3(NQKV / 32, DIM / 32), dim3(32, 8)>>>(w_qkv);
    tconv_wo_kernel<<<dim3(DIM / 32, DIM / 32), dim3(32, 8)>>>(w_out);

    // 1) QKV projection (HMMA fp16 2-term, scatter into g_Q/g_K/g_V)
    cudaFuncSetAttribute(gemm_mma_kernel, cudaFuncAttributeMaxDynamicSharedMemorySize, GEMM_SMEM);
    gemm_mma_kernel<<<dim3(NQKV / 128, SEQ / 128), 128, GEMM_SMEM>>>(nullptr, 0);

    // 2) Sparse attention (fp32, writes split-fp16 attn output)
    const int attn_smem = 4 * 64 * SP * (int)sizeof(float);
    cudaFuncSetAttribute(attn_kernel, cudaFuncAttributeMaxDynamicSharedMemorySize, attn_smem);
    attn_kernel<<<dim3(SEQ / 64, NH), 256, attn_smem>>>();

    // 3) Output projection (HMMA fp16 2-term)
    gemm_mma_kernel<<<dim3(DIM / 128, SEQ / 128), 128, GEMM_SMEM>>>(out, 1);
}

// round 14
// speedup vs baseline: 1.7724x; 1.4929x over previous
#include <cuda_runtime.h>
#include <cuda_fp16.h>
#include <cstdint>
#include <math.h>

// Problem constants
#define SEQ   4096
#define NH    16
#define HD    64
#define DIM   1024
#define NQKV  3072
#define WIN_HALF 128
#define NGLOB 64

// ---------------------------------------------------------------------------
// Device-global scratch (allocation-free rule)
// ---------------------------------------------------------------------------
__device__ float g_Q[NH * SEQ * HD];               // [H][S][D] fp32
__device__ float g_K[NH * SEQ * HD];
__device__ float g_V[NH * SEQ * HD];
__device__ __half g_x[SEQ * DIM];                  // x fp16 [S][K]
__device__ __half g_wqT[NQKV * DIM];               // w_qkv^T fp16 [N][K]
__device__ __half g_woT[DIM * DIM];                // w_out^T fp16 [N][K]
__device__ __half g_a[SEQ * DIM];                  // attn out fp16 [S][H*D]

// ---------------------------------------------------------------------------
// Baseline-PTX helpers (sm_80+ baseline only; harness compiles at compute_103)
// ---------------------------------------------------------------------------
__device__ __forceinline__ uint32_t smem_to_u32(const void* smem_ptr) {
    uint32_t addr;
    asm("{ .reg .u64 tmp; cvta.to.shared.u64 tmp, %1; cvt.u32.u64 %0, tmp; }"
        : "=r"(addr) : "l"(smem_ptr));
    return addr;
}

__device__ __forceinline__ void cp_async16(uint32_t dst, const void* src) {
    asm volatile("cp.async.cg.shared.global [%0], [%1], 16;"
                 :: "r"(dst), "l"(src));
}
#define CP_ASYNC_COMMIT() asm volatile("cp.async.commit_group;" ::: "memory")
#define CP_ASYNC_WAIT_2() asm volatile("cp.async.wait_group 2;" ::: "memory")

__device__ __forceinline__ void ldsm_x4(uint32_t& r0, uint32_t& r1,
                                        uint32_t& r2, uint32_t& r3, uint32_t addr) {
    asm volatile("ldmatrix.sync.aligned.m8n8.x4.shared.b16 {%0,%1,%2,%3}, [%4];"
                 : "=r"(r0), "=r"(r1), "=r"(r2), "=r"(r3) : "r"(addr));
}

__device__ __forceinline__ void mma_f16(float* c, const uint32_t* a, const uint32_t* b) {
    asm volatile(
        "mma.sync.aligned.m16n8k16.row.col.f32.f16.f16.f32 "
        "{%0,%1,%2,%3}, {%4,%5,%6,%7}, {%8,%9}, {%0,%1,%2,%3};"
        : "+f"(c[0]), "+f"(c[1]), "+f"(c[2]), "+f"(c[3])
        : "r"(a[0]), "r"(a[1]), "r"(a[2]), "r"(a[3]), "r"(b[0]), "r"(b[1]));
}

// ---------------------------------------------------------------------------
// Pre-pass 1: round x -> g_x (fp16)
// ---------------------------------------------------------------------------
__global__ void conv_x_kernel(const float* __restrict__ x) {
    const int i = (blockIdx.x * blockDim.x + threadIdx.x) * 4;
    float4 v = *reinterpret_cast<const float4*>(x + i);
    g_x[i + 0] = __float2half_rn(v.x);
    g_x[i + 1] = __float2half_rn(v.y);
    g_x[i + 2] = __float2half_rn(v.z);
    g_x[i + 3] = __float2half_rn(v.w);
}

// ---------------------------------------------------------------------------
// Pre-pass 2: transpose W[K][N] -> [N][K] fp16 (round-to-nearest)
// ---------------------------------------------------------------------------
__global__ void tconv_wq_kernel(const float* __restrict__ W) {
    __shared__ float t[32][33];
    const int n0 = blockIdx.x * 32, k0 = blockIdx.y * 32;
    const int tx = threadIdx.x, ty = threadIdx.y;
#pragma unroll
    for (int i = 0; i < 32; i += 8)
        t[ty + i][tx] = W[(size_t)(k0 + ty + i) * NQKV + n0 + tx];
    __syncthreads();
#pragma unroll
    for (int i = 0; i < 32; i += 8)
        g_wqT[(size_t)(n0 + ty + i) * DIM + k0 + tx] = __float2half_rn(t[tx][ty + i]);
}

__global__ void tconv_wo_kernel(const float* __restrict__ W) {
    __shared__ float t[32][33];
    const int n0 = blockIdx.x * 32, k0 = blockIdx.y * 32;
    const int tx = threadIdx.x, ty = threadIdx.y;
#pragma unroll
    for (int i = 0; i < 32; i += 8)
        t[ty + i][tx] = W[(size_t)(k0 + ty + i) * DIM + n0 + tx];
    __syncthreads();
#pragma unroll
    for (int i = 0; i < 32; i += 8)
        g_woT[(size_t)(n0 + ty + i) * DIM + k0 + tx] = __float2half_rn(t[tx][ty + i]);
}

// ---------------------------------------------------------------------------
// HMMA GEMM: C[M x N] = A[M x 1024] @ B^T (A, B fp16; B stored [N][1024])
// Single-term plain fp16, fp32 accumulate, m16n8k16.
// CTA tile 128x128, BK=32, 128 threads (4 warps, warp tile 64x64).
// cp.async 3-stage pipeline. mode 0: scatter Q/K/V; 1: write Cout.
// ---------------------------------------------------------------------------
#define AP_BYTES   80        // padded row pitch (32 fp16 -> 40 elems = 80B)
#define T_TILE     10240     // one 128-row tile: 128 * 80
#define STAGE_B    20480     // 2 tiles (A, B)
#define N_STAGE    3
#define GEMM_SMEM  (N_STAGE * STAGE_B)

__global__ void __launch_bounds__(128) gemm_mma_kernel(float* __restrict__ Cout, int mode)
{
    extern __shared__ char smem_raw[];
    const uint32_t sb = smem_to_u32(smem_raw);

    const int tid  = threadIdx.x;
    const int wid  = tid >> 5;
    const int lane = tid & 31;
    const int wm   = wid & 1;        // 0..1  (M, 64 rows)
    const int wn   = wid >> 1;       // 0..1  (N, 64 cols)
    const int m0   = blockIdx.y * 128;
    const int n0   = blockIdx.x * 128;

    const __half *A, *B;
    if (mode == 0) { A = g_x; B = g_wqT; }
    else           { A = g_a; B = g_woT; }

    // Loader: 1024 chunks of 16B per stage, 8 per thread.
    auto load_stage = [&](int stage, int kt) {
        const int k0 = kt * 32;
        const uint32_t sbase = sb + stage * STAGE_B;
#pragma unroll
        for (int e = 0; e < 8; e++) {
            const int cid  = e * 128 + tid;      // 0..1023
            const int tile = cid >> 9;           // 0:A 1:B
            const int idx  = cid & 511;
            const int r    = idx >> 2;           // row 0..127
            const int ch   = idx & 3;            // 16B chunk
            const __half* src = (tile == 0)
                ? A + (size_t)(m0 + r) * DIM + k0 + ch * 8
                : B + (size_t)(n0 + r) * DIM + k0 + ch * 8;
            cp_async16(sbase + tile * T_TILE + r * AP_BYTES + ch * 16, src);
        }
    };

    const uint32_t a_off = (uint32_t)((wm * 64 + (lane & 15)) * AP_BYTES + (lane >> 4) * 16);
    const uint32_t b_off = (uint32_t)((wn * 64 + (lane & 15)) * AP_BYTES + (lane >> 4) * 16) + (uint32_t)T_TILE;

    float acc[4][8][4];
#pragma unroll
    for (int i = 0; i < 4; i++)
#pragma unroll
        for (int j = 0; j < 8; j++)
#pragma unroll
            for (int e = 0; e < 4; e++) acc[i][j][e] = 0.0f;

    load_stage(0, 0); CP_ASYNC_COMMIT();
    load_stage(1, 1); CP_ASYNC_COMMIT();
    load_stage(2, 2); CP_ASYNC_COMMIT();

    int stg = 0;
    for (int kt = 0; kt < 32; kt++) {
        CP_ASYNC_WAIT_2();
        __syncthreads();
        const uint32_t sbase = sb + (uint32_t)stg * STAGE_B;

#pragma unroll
        for (int ks = 0; ks < 2; ks++) {
            uint32_t ah[4][4], bh[8][2];
#pragma unroll
            for (int i = 0; i < 4; i++) {
                const uint32_t ad = sbase + a_off + i * (16 * AP_BYTES) + ks * 32;
                ldsm_x4(ah[i][0], ah[i][1], ah[i][2], ah[i][3], ad);
            }
#pragma unroll
            for (int p = 0; p < 4; p++) {
                const uint32_t bd = sbase + b_off + p * (16 * AP_BYTES) + ks * 32;
                uint32_t t0, t1, t2, t3;
                ldsm_x4(t0, t1, t2, t3, bd);
                bh[2*p][0] = t0; bh[2*p][1] = t2; bh[2*p+1][0] = t1; bh[2*p+1][1] = t3;
            }
            // One pass of 32 independent MMAs
#pragma unroll
            for (int i = 0; i < 4; i++)
#pragma unroll
                for (int j = 0; j < 8; j++) mma_f16(acc[i][j], ah[i], bh[j]);
        }

        __syncthreads();
        if (kt + 3 < 32) load_stage(stg, kt + 3);
        CP_ASYNC_COMMIT();
        stg = (stg == N_STAGE - 1) ? 0 : stg + 1;
    }

    const int mbase = m0 + wm * 64 + (lane >> 2);
    const int nbase = n0 + wn * 64 + (lane & 3) * 2;
#pragma unroll
    for (int i = 0; i < 4; i++) {
        const int mlo = mbase + i * 16;
#pragma unroll
        for (int j = 0; j < 8; j++) {
            const int n = nbase + j * 8;
            if (mode == 0) {
                const int t = n >> 10, rem = n & 1023, h = rem >> 6, d = rem & 63;
                float* base = (t == 0 ? g_Q : (t == 1 ? g_K : g_V)) + (size_t)h * SEQ * HD + d;
                float2 v0; v0.x = acc[i][j][0]; v0.y = acc[i][j][1];
                float2 v1; v1.x = acc[i][j][2]; v1.y = acc[i][j][3];
                *reinterpret_cast<float2*>(base + (size_t)mlo * HD)       = v0;
                *reinterpret_cast<float2*>(base + (size_t)(mlo + 8) * HD) = v1;
            } else {
                float2 v0; v0.x = acc[i][j][0]; v0.y = acc[i][j][1];
                float2 v1; v1.x = acc[i][j][2]; v1.y = acc[i][j][3];
                *reinterpret_cast<float2*>(Cout + (size_t)mlo * DIM + n)       = v0;
                *reinterpret_cast<float2*>(Cout + (size_t)(mlo + 8) * DIM + n) = v1;
            }
        }
    }
}

// ---------------------------------------------------------------------------
// Attention: flash-style online softmax over <=4 key tiles of 64.
// fp32 math; float4 global loads; epilogue writes fp16 into g_a.
// ---------------------------------------------------------------------------
#define SP 65

__global__ void attn_kernel()
{
    extern __shared__ float sm[];
    float* Qs = sm;
    float* Ks = Qs + 64 * SP;
    float* Vs = Ks + 64 * SP;
    float* Ss = Vs + 64 * SP;

    const int h  = blockIdx.y;
    const int qt = blockIdx.x;
    const int qbase = qt * 64;

    const int tid = threadIdx.x;
    const int ty = tid >> 4;
    const int tx = tid & 15;

    const float* Qh = g_Q + (size_t)h * SEQ * HD;
    const float* Kh = g_K + (size_t)h * SEQ * HD;
    const float* Vh = g_V + (size_t)h * SEQ * HD;

#pragma unroll
    for (int e = 0; e < 4; e++) {
        const int idx = tid + e * 256;
        const int r = idx >> 4, c4 = (idx & 15) * 4;
        float4 v = *reinterpret_cast<const float4*>(Qh + (size_t)(qbase + r) * HD + c4);
        float* d = Qs + r * SP + c4;
        d[0] = v.x; d[1] = v.y; d[2] = v.z; d[3] = v.w;
    }

    float m_r[4], l_r[4], acc[4][4];
#pragma unroll
    for (int i = 0; i < 4; i++) {
        m_r[i] = -1e30f;
        l_r[i] = 0.0f;
#pragma unroll
        for (int j = 0; j < 4; j++) acc[i][j] = 0.0f;
    }

    int starts[4];
    int ns = 0;
    starts[ns++] = 0;
    if (qbase - 128 > 0) starts[ns++] = qbase - 128;
    if (qbase - 64  > 0) starts[ns++] = qbase - 64;
    if (qbase       > 0) starts[ns++] = qbase;

    const float scale = 0.125f;

    for (int it = 0; it < ns; it++) {
        const int kst = starts[it];
        __syncthreads();
#pragma unroll
        for (int e = 0; e < 4; e++) {
            const int idx = tid + e * 256;
            const int r = idx >> 4, c4 = (idx & 15) * 4;
            float4 kv = *reinterpret_cast<const float4*>(Kh + (size_t)(kst + r) * HD + c4);
            float4 vv = *reinterpret_cast<const float4*>(Vh + (size_t)(kst + r) * HD + c4);
            float* dk = Ks + r * SP + c4;
            float* dv = Vs + r * SP + c4;
            dk[0] = kv.x; dk[1] = kv.y; dk[2] = kv.z; dk[3] = kv.w;
            dv[0] = vv.x; dv[1] = vv.y; dv[2] = vv.z; dv[3] = vv.w;
        }
        __syncthreads();

        float sc[4][4];
#pragma unroll
        for (int i = 0; i < 4; i++)
#pragma unroll
            for (int j = 0; j < 4; j++) sc[i][j] = 0.0f;

#pragma unroll 8
        for (int d = 0; d < 64; d++) {
            float a[4], b[4];
#pragma unroll
            for (int i = 0; i < 4; i++) a[i] = Qs[(ty * 4 + i) * SP + d];
#pragma unroll
            for (int j = 0; j < 4; j++) b[j] = Ks[(tx * 4 + j) * SP + d];
#pragma unroll
            for (int i = 0; i < 4; i++)
#pragma unroll
                for (int j = 0; j < 4; j++) sc[i][j] = fmaf(a[i], b[j], sc[i][j]);
        }

        float tmax[4];
#pragma unroll
        for (int i = 0; i < 4; i++) {
            const int iq = qbase + ty * 4 + i;
            float mx = -1e30f;
#pragma unroll
            for (int j = 0; j < 4; j++) {
                const int jk = kst + tx * 4 + j;
                const bool valid = (jk <= iq) && ((jk >= iq - WIN_HALF) || (jk < NGLOB));
                const float v = valid ? sc[i][j] * scale : -1e30f;
                sc[i][j] = v;
                mx = fmaxf(mx, v);
            }
            tmax[i] = mx;
        }

#pragma unroll
        for (int off = 1; off < 16; off <<= 1)
#pragma unroll
            for (int i = 0; i < 4; i++)
                tmax[i] = fmaxf(tmax[i], __shfl_xor_sync(0xffffffffu, tmax[i], off));

        float psum[4];
#pragma unroll
        for (int i = 0; i < 4; i++) {
            const float mnew = fmaxf(m_r[i], tmax[i]);
            const float alpha = __expf(m_r[i] - mnew);
            m_r[i] = mnew;
            float ps = 0.0f;
#pragma unroll
            for (int j = 0; j < 4; j++) {
                const float p = __expf(sc[i][j] - mnew);
                sc[i][j] = p;
                ps += p;
            }
            psum[i] = ps;
            l_r[i] *= alpha;
#pragma unroll
            for (int j = 0; j < 4; j++) acc[i][j] *= alpha;
        }
#pragma unroll
        for (int off = 1; off < 16; off <<= 1)
#pragma unroll
            for (int i = 0; i < 4; i++)
                psum[i] += __shfl_xor_sync(0xffffffffu, psum[i], off);
#pragma unroll
        for (int i = 0; i < 4; i++) l_r[i] += psum[i];

#pragma unroll
        for (int i = 0; i < 4; i++)
#pragma unroll
            for (int j = 0; j < 4; j++)
                Ss[(ty * 4 + i) * SP + tx * 4 + j] = sc[i][j];
        __syncthreads();

#pragma unroll 8
        for (int c = 0; c < 64; c++) {
            float a[4], b[4];
#pragma unroll
            for (int j = 0; j < 4; j++) b[j] = Vs[c * SP + tx * 4 + j];
#pragma unroll
            for (int i = 0; i < 4; i++) a[i] = Ss[(ty * 4 + i) * SP + c];
#pragma unroll
            for (int i = 0; i < 4; i++)
#pragma unroll
                for (int j = 0; j < 4; j++) acc[i][j] = fmaf(a[i], b[j], acc[i][j]);
        }
    }

    // Normalize + store fp16 to g_a [S][H*D]
#pragma unroll
    for (int i = 0; i < 4; i++) {
        const int s = qbase + ty * 4 + i;
        const float inv = 1.0f / l_r[i];
#pragma unroll
        for (int j = 0; j < 4; j++) {
            const float o = acc[i][j] * inv;
            const size_t oi = (size_t)s * DIM + h * HD + tx * 4 + j;
            g_a[oi] = __float2half_rn(o);
        }
    }
}

// ---------------------------------------------------------------------------
// Launcher
// ---------------------------------------------------------------------------
extern "C" void kernel_launch(void* const* d_in, const int* in_sizes, int n_in,
                              void* d_out, int out_size)
{
    const float* x     = (const float*)d_in[0];   // [1,4096,1024]
    const float* w_qkv = (const float*)d_in[1];   // [1024,3072]
    const float* w_out = (const float*)d_in[2];   // [1024,1024]
    float* out = (float*)d_out;                   // [1,4096,1024]

    // Pre-pass: round x to fp16; transpose+round weights to fp16
    conv_x_kernel<<<SEQ * DIM / 4 / 256, 256>>>(x);
    tconv_wq_kernel<<<dim3(NQKV / 32, DIM / 32), dim3(32, 8)>>>(w_qkv);
    tconv_wo_kernel<<<dim3(DIM / 32, DIM / 32), dim3(32, 8)>>>(w_out);

    // 1) QKV projection (HMMA fp16, scatter into g_Q/g_K/g_V)
    cudaFuncSetAttribute(gemm_mma_kernel, cudaFuncAttributeMaxDynamicSharedMemorySize, GEMM_SMEM);
    gemm_mma_kernel<<<dim3(NQKV / 128, SEQ / 128), 128, GEMM_SMEM>>>(nullptr, 0);

    // 2) Sparse attention (fp32, writes fp16 attn output)
    const int attn_smem = 4 * 64 * SP * (int)sizeof(float);
    cudaFuncSetAttribute(attn_kernel, cudaFuncAttributeMaxDynamicSharedMemorySize, attn_smem);
    attn_kernel<<<dim3(SEQ / 64, NH), 256, attn_smem>>>();

    // 3) Output projection (HMMA fp16)
    gemm_mma_kernel<<<dim3(DIM / 128, SEQ / 128), 128, GEMM_SMEM>>>(out, 1);
}

// round 16
// speedup vs baseline: 2.5952x; 1.4642x over previous
#include <cuda_runtime.h>
#include <cuda_fp16.h>
#include <cstdint>
#include <math.h>

// Problem constants
#define SEQ   4096
#define NH    16
#define HD    64
#define DIM   1024
#define NQKV  3072
#define WIN_HALF 128
#define NGLOB 64

// ---------------------------------------------------------------------------
// Device-global scratch (allocation-free rule)
// ---------------------------------------------------------------------------
__device__ float g_Q[NH * SEQ * HD];               // [H][S][D] fp32
__device__ float g_K[NH * SEQ * HD];
__device__ float g_V[NH * SEQ * HD];
__device__ __half g_x[SEQ * DIM];                  // x fp16 [S][K]
__device__ __half g_wqT[NQKV * DIM];               // w_qkv^T fp16 [N][K]
__device__ __half g_woT[DIM * DIM];                // w_out^T fp16 [N][K]
__device__ __half g_a[SEQ * DIM];                  // attn out fp16 [S][H*D]

// ---------------------------------------------------------------------------
// Baseline-PTX helpers (sm_80+ baseline only; harness compiles at compute_103)
// ---------------------------------------------------------------------------
__device__ __forceinline__ uint32_t smem_to_u32(const void* smem_ptr) {
    uint32_t addr;
    asm("{ .reg .u64 tmp; cvta.to.shared.u64 tmp, %1; cvt.u32.u64 %0, tmp; }"
        : "=r"(addr) : "l"(smem_ptr));
    return addr;
}

__device__ __forceinline__ void cp_async16(uint32_t dst, const void* src) {
    asm volatile("cp.async.cg.shared.global [%0], [%1], 16;"
                 :: "r"(dst), "l"(src));
}
#define CP_ASYNC_COMMIT() asm volatile("cp.async.commit_group;" ::: "memory")
#define CP_ASYNC_WAIT_2() asm volatile("cp.async.wait_group 2;" ::: "memory")

__device__ __forceinline__ void ldsm_x4(uint32_t& r0, uint32_t& r1,
                                        uint32_t& r2, uint32_t& r3, uint32_t addr) {
    asm volatile("ldmatrix.sync.aligned.m8n8.x4.shared.b16 {%0,%1,%2,%3}, [%4];"
                 : "=r"(r0), "=r"(r1), "=r"(r2), "=r"(r3) : "r"(addr));
}

__device__ __forceinline__ void ldsm_x4_t(uint32_t& r0, uint32_t& r1,
                                          uint32_t& r2, uint32_t& r3, uint32_t addr) {
    asm volatile("ldmatrix.sync.aligned.m8n8.x4.trans.shared.b16 {%0,%1,%2,%3}, [%4];"
                 : "=r"(r0), "=r"(r1), "=r"(r2), "=r"(r3) : "r"(addr));
}

__device__ __forceinline__ void mma_f16(float* c, const uint32_t* a, const uint32_t* b) {
    asm volatile(
        "mma.sync.aligned.m16n8k16.row.col.f32.f16.f16.f32 "
        "{%0,%1,%2,%3}, {%4,%5,%6,%7}, {%8,%9}, {%0,%1,%2,%3};"
        : "+f"(c[0]), "+f"(c[1]), "+f"(c[2]), "+f"(c[3])
        : "r"(a[0]), "r"(a[1]), "r"(a[2]), "r"(a[3]), "r"(b[0]), "r"(b[1]));
}

__device__ __forceinline__ void split_h(float v, __half& h, __half& l) {
    h = __float2half_rn(v);
    l = __float2half_rn(v - __half2float(h));
}

__device__ __forceinline__ uint32_t pack_h2(__half a, __half b) {
    __half2 t = __halves2half2(a, b);
    return *reinterpret_cast<uint32_t*>(&t);
}

// ---------------------------------------------------------------------------
// Pre-pass 1: round x -> g_x (fp16)
// ---------------------------------------------------------------------------
__global__ void conv_x_kernel(const float* __restrict__ x) {
    const int i = (blockIdx.x * blockDim.x + threadIdx.x) * 4;
    float4 v = *reinterpret_cast<const float4*>(x + i);
    g_x[i + 0] = __float2half_rn(v.x);
    g_x[i + 1] = __float2half_rn(v.y);
    g_x[i + 2] = __float2half_rn(v.z);
    g_x[i + 3] = __float2half_rn(v.w);
}

// ---------------------------------------------------------------------------
// Pre-pass 2: transpose W[K][N] -> [N][K] fp16 (round-to-nearest)
// ---------------------------------------------------------------------------
__global__ void tconv_wq_kernel(const float* __restrict__ W) {
    __shared__ float t[32][33];
    const int n0 = blockIdx.x * 32, k0 = blockIdx.y * 32;
    const int tx = threadIdx.x, ty = threadIdx.y;
#pragma unroll
    for (int i = 0; i < 32; i += 8)
        t[ty + i][tx] = W[(size_t)(k0 + ty + i) * NQKV + n0 + tx];
    __syncthreads();
#pragma unroll
    for (int i = 0; i < 32; i += 8)
        g_wqT[(size_t)(n0 + ty + i) * DIM + k0 + tx] = __float2half_rn(t[tx][ty + i]);
}

__global__ void tconv_wo_kernel(const float* __restrict__ W) {
    __shared__ float t[32][33];
    const int n0 = blockIdx.x * 32, k0 = blockIdx.y * 32;
    const int tx = threadIdx.x, ty = threadIdx.y;
#pragma unroll
    for (int i = 0; i < 32; i += 8)
        t[ty + i][tx] = W[(size_t)(k0 + ty + i) * DIM + n0 + tx];
    __syncthreads();
#pragma unroll
    for (int i = 0; i < 32; i += 8)
        g_woT[(size_t)(n0 + ty + i) * DIM + k0 + tx] = __float2half_rn(t[tx][ty + i]);
}

// ---------------------------------------------------------------------------
// HMMA GEMM (unchanged from R14): single-term fp16, 128x128 tile, BK=32,
// 128 threads, 3-stage cp.async. mode 0: scatter Q/K/V; 1: write Cout.
// ---------------------------------------------------------------------------
#define AP_BYTES   80
#define T_TILE     10240
#define STAGE_B    20480
#define N_STAGE    3
#define GEMM_SMEM  (N_STAGE * STAGE_B)

__global__ void __launch_bounds__(128) gemm_mma_kernel(float* __restrict__ Cout, int mode)
{
    extern __shared__ char smem_raw[];
    const uint32_t sb = smem_to_u32(smem_raw);

    const int tid  = threadIdx.x;
    const int wid  = tid >> 5;
    const int lane = tid & 31;
    const int wm   = wid & 1;
    const int wn   = wid >> 1;
    const int m0   = blockIdx.y * 128;
    const int n0   = blockIdx.x * 128;

    const __half *A, *B;
    if (mode == 0) { A = g_x; B = g_wqT; }
    else           { A = g_a; B = g_woT; }

    auto load_stage = [&](int stage, int kt) {
        const int k0 = kt * 32;
        const uint32_t sbase = sb + stage * STAGE_B;
#pragma unroll
        for (int e = 0; e < 8; e++) {
            const int cid  = e * 128 + tid;
            const int tile = cid >> 9;
            const int idx  = cid & 511;
            const int r    = idx >> 2;
            const int ch   = idx & 3;
            const __half* src = (tile == 0)
                ? A + (size_t)(m0 + r) * DIM + k0 + ch * 8
                : B + (size_t)(n0 + r) * DIM + k0 + ch * 8;
            cp_async16(sbase + tile * T_TILE + r * AP_BYTES + ch * 16, src);
        }
    };

    const uint32_t a_off = (uint32_t)((wm * 64 + (lane & 15)) * AP_BYTES + (lane >> 4) * 16);
    const uint32_t b_off = (uint32_t)((wn * 64 + (lane & 15)) * AP_BYTES + (lane >> 4) * 16) + (uint32_t)T_TILE;

    float acc[4][8][4];
#pragma unroll
    for (int i = 0; i < 4; i++)
#pragma unroll
        for (int j = 0; j < 8; j++)
#pragma unroll
            for (int e = 0; e < 4; e++) acc[i][j][e] = 0.0f;

    load_stage(0, 0); CP_ASYNC_COMMIT();
    load_stage(1, 1); CP_ASYNC_COMMIT();
    load_stage(2, 2); CP_ASYNC_COMMIT();

    int stg = 0;
    for (int kt = 0; kt < 32; kt++) {
        CP_ASYNC_WAIT_2();
        __syncthreads();
        const uint32_t sbase = sb + (uint32_t)stg * STAGE_B;

#pragma unroll
        for (int ks = 0; ks < 2; ks++) {
            uint32_t ah[4][4], bh[8][2];
#pragma unroll
            for (int i = 0; i < 4; i++) {
                const uint32_t ad = sbase + a_off + i * (16 * AP_BYTES) + ks * 32;
                ldsm_x4(ah[i][0], ah[i][1], ah[i][2], ah[i][3], ad);
            }
#pragma unroll
            for (int p = 0; p < 4; p++) {
                const uint32_t bd = sbase + b_off + p * (16 * AP_BYTES) + ks * 32;
                uint32_t t0, t1, t2, t3;
                ldsm_x4(t0, t1, t2, t3, bd);
                bh[2*p][0] = t0; bh[2*p][1] = t2; bh[2*p+1][0] = t1; bh[2*p+1][1] = t3;
            }
#pragma unroll
            for (int i = 0; i < 4; i++)
#pragma unroll
                for (int j = 0; j < 8; j++) mma_f16(acc[i][j], ah[i], bh[j]);
        }

        __syncthreads();
        if (kt + 3 < 32) load_stage(stg, kt + 3);
        CP_ASYNC_COMMIT();
        stg = (stg == N_STAGE - 1) ? 0 : stg + 1;
    }

    const int mbase = m0 + wm * 64 + (lane >> 2);
    const int nbase = n0 + wn * 64 + (lane & 3) * 2;
#pragma unroll
    for (int i = 0; i < 4; i++) {
        const int mlo = mbase + i * 16;
#pragma unroll
        for (int j = 0; j < 8; j++) {
            const int n = nbase + j * 8;
            if (mode == 0) {
                const int t = n >> 10, rem = n & 1023, h = rem >> 6, d = rem & 63;
                float* base = (t == 0 ? g_Q : (t == 1 ? g_K : g_V)) + (size_t)h * SEQ * HD + d;
                float2 v0; v0.x = acc[i][j][0]; v0.y = acc[i][j][1];
                float2 v1; v1.x = acc[i][j][2]; v1.y = acc[i][j][3];
                *reinterpret_cast<float2*>(base + (size_t)mlo * HD)       = v0;
                *reinterpret_cast<float2*>(base + (size_t)(mlo + 8) * HD) = v1;
            } else {
                float2 v0; v0.x = acc[i][j][0]; v0.y = acc[i][j][1];
                float2 v1; v1.x = acc[i][j][2]; v1.y = acc[i][j][3];
                *reinterpret_cast<float2*>(Cout + (size_t)mlo * DIM + n)       = v0;
                *reinterpret_cast<float2*>(Cout + (size_t)(mlo + 8) * DIM + n) = v1;
            }
        }
    }
}

// ---------------------------------------------------------------------------
// Attention on HMMA: flash-style online softmax over <=4 key tiles of 64.
// QK^T 3-term split fp16 (Qh*Kh + Ql*Kh + Qh*Kl); P*V 2-term ((Ph+Pl)*Vh).
// 128 threads (4 warps); each warp owns 16 query rows.
// V consumed via ldmatrix.trans from row-major [k][d] smem.
// ---------------------------------------------------------------------------
#define APH       72                     // smem pitch in halves (144 B)
#define QSH_B     0
#define QSL_B     (64 * APH * 2)         //  9216
#define KSH_B     (2 * 64 * APH * 2)     // 18432
#define KSL_B     (3 * 64 * APH * 2)     // 27648
#define VSH_B     (4 * 64 * APH * 2)     // 36864
#define ATTN_SMEM (5 * 64 * APH * 2)     // 46080 bytes

__global__ void __launch_bounds__(128) attn_kernel()
{
    extern __shared__ __half smh[];
    const uint32_t sb = smem_to_u32(smh);

    const int h  = blockIdx.y;
    const int qt = blockIdx.x;
    const int qbase = qt * 64;

    const int tid  = threadIdx.x;
    const int w    = tid >> 5;
    const int lane = tid & 31;

    const float* Qh_p = g_Q + (size_t)h * SEQ * HD;
    const float* Kh_p = g_K + (size_t)h * SEQ * HD;
    const float* Vh_p = g_V + (size_t)h * SEQ * HD;

    // Load Q tile [64x64] fp32 -> split fp16 hi/lo in smem.
    // 64 rows x 16 float4-chunks = 1024 chunks; 128 threads x 8 iters.
#pragma unroll
    for (int e = 0; e < 8; e++) {
        const int idx = tid + e * 128;          // 0..1023
        const int r = idx >> 4, c4 = (idx & 15) * 4;
        float4 v = *reinterpret_cast<const float4*>(Qh_p + (size_t)(qbase + r) * HD + c4);
        __half h0, h1, h2, h3, l0, l1, l2, l3;
        split_h(v.x, h0, l0); split_h(v.y, h1, l1);
        split_h(v.z, h2, l2); split_h(v.w, h3, l3);
        __half* dh = smh + r * APH + c4;                 // QSH
        __half* dl = smh + (QSL_B / 2) + r * APH + c4;   // QSL
        reinterpret_cast<__half2*>(dh)[0] = __halves2half2(h0, h1);
        reinterpret_cast<__half2*>(dh)[1] = __halves2half2(h2, h3);
        reinterpret_cast<__half2*>(dl)[0] = __halves2half2(l0, l1);
        reinterpret_cast<__half2*>(dl)[1] = __halves2half2(l2, l3);
    }

    float acc_o[8][4];
#pragma unroll
    for (int j = 0; j < 8; j++)
#pragma unroll
        for (int e = 0; e < 4; e++) acc_o[j][e] = 0.0f;
    float m_r[2] = {-1e30f, -1e30f};
    float l_r[2] = {0.0f, 0.0f};

    int starts[4];
    int ns = 0;
    starts[ns++] = 0;
    if (qbase - 128 > 0) starts[ns++] = qbase - 128;
    if (qbase - 64  > 0) starts[ns++] = qbase - 64;
    if (qbase       > 0) starts[ns++] = qbase;

    const int r0 = qbase + w * 16 + (lane >> 2);   // global query row (low)

    for (int it = 0; it < ns; it++) {
        const int kst = starts[it];
        __syncthreads();   // previous tile's smem consumers done

        // Load K (split hi/lo) and V (hi) tiles [64x64]: 1024 chunks each.
#pragma unroll
        for (int e = 0; e < 8; e++) {
            const int idx = tid + e * 128;
            const int r = idx >> 4, c4 = (idx & 15) * 4;
            float4 kv = *reinterpret_cast<const float4*>(Kh_p + (size_t)(kst + r) * HD + c4);
            float4 vv = *reinterpret_cast<const float4*>(Vh_p + (size_t)(kst + r) * HD + c4);
            __half h0, h1, h2, h3, l0, l1, l2, l3;
            split_h(kv.x, h0, l0); split_h(kv.y, h1, l1);
            split_h(kv.z, h2, l2); split_h(kv.w, h3, l3);
            __half* dh = smh + (KSH_B / 2) + r * APH + c4;
            __half* dl = smh + (KSL_B / 2) + r * APH + c4;
            reinterpret_cast<__half2*>(dh)[0] = __halves2half2(h0, h1);
            reinterpret_cast<__half2*>(dh)[1] = __halves2half2(h2, h3);
            reinterpret_cast<__half2*>(dl)[0] = __halves2half2(l0, l1);
            reinterpret_cast<__half2*>(dl)[1] = __halves2half2(l2, l3);
            __half* dv = smh + (VSH_B / 2) + r * APH + c4;
            reinterpret_cast<__half2*>(dv)[0] =
                __halves2half2(__float2half_rn(vv.x), __float2half_rn(vv.y));
            reinterpret_cast<__half2*>(dv)[1] =
                __halves2half2(__float2half_rn(vv.z), __float2half_rn(vv.w));
        }
        __syncthreads();

        // ---- S = Q K^T  (3-term split) ----
        float s[8][4];
#pragma unroll
        for (int j = 0; j < 8; j++)
#pragma unroll
            for (int e = 0; e < 4; e++) s[j][e] = 0.0f;

        const uint32_t arow = (uint32_t)((w * 16 + (lane & 15)) * (APH * 2) + (lane >> 4) * 16);
        const uint32_t brow = (uint32_t)(((lane & 15)) * (APH * 2) + (lane >> 4) * 16);

#pragma unroll
        for (int kk = 0; kk < 4; kk++) {
            uint32_t aqh[4], aql[4];
            ldsm_x4(aqh[0], aqh[1], aqh[2], aqh[3], sb + QSH_B + arow + kk * 32);
            ldsm_x4(aql[0], aql[1], aql[2], aql[3], sb + QSL_B + arow + kk * 32);
#pragma unroll
            for (int p = 0; p < 4; p++) {
                uint32_t t0, t1, t2, t3;
                uint32_t bh[2], bl[2];
                const uint32_t koff = (uint32_t)(p * 16 * (APH * 2)) + kk * 32;
                ldsm_x4(t0, t1, t2, t3, sb + KSH_B + brow + koff);
                bh[0] = t0; bh[1] = t2;
                uint32_t bh1[2]; bh1[0] = t1; bh1[1] = t3;
                ldsm_x4(t0, t1, t2, t3, sb + KSL_B + brow + koff);
                bl[0] = t0; bl[1] = t2;
                uint32_t bl1[2]; bl1[0] = t1; bl1[1] = t3;
                mma_f16(s[2*p],   aqh, bh);
                mma_f16(s[2*p+1], aqh, bh1);
                mma_f16(s[2*p],   aql, bh);
                mma_f16(s[2*p+1], aql, bh1);
                mma_f16(s[2*p],   aqh, bl);
                mma_f16(s[2*p+1], aqh, bl1);
            }
        }

        // ---- mask + scale + online softmax (fp32 on fragments) ----
        const int colb = kst + (lane & 3) * 2;
        float mx[2] = {-1e30f, -1e30f};
#pragma unroll
        for (int j = 0; j < 8; j++) {
            const int c0 = colb + j * 8;
#pragma unroll
            for (int e = 0; e < 4; e++) {
                const int col = c0 + (e & 1);
                const int row = (e < 2) ? r0 : (r0 + 8);
                const bool valid = (col <= row) && ((col >= row - WIN_HALF) || (col < NGLOB));
                const float v = valid ? s[j][e] * 0.125f : -1e30f;
                s[j][e] = v;
                mx[e >> 1] = fmaxf(mx[e >> 1], v);
            }
        }
#pragma unroll
        for (int off = 1; off < 4; off <<= 1) {
            mx[0] = fmaxf(mx[0], __shfl_xor_sync(0xffffffffu, mx[0], off));
            mx[1] = fmaxf(mx[1], __shfl_xor_sync(0xffffffffu, mx[1], off));
        }
        float alpha[2], psum[2];
#pragma unroll
        for (int e = 0; e < 2; e++) {
            const float mnew = fmaxf(m_r[e], mx[e]);
            alpha[e] = __expf(m_r[e] - mnew);
            m_r[e] = mnew;
            l_r[e] *= alpha[e];
            psum[e] = 0.0f;
        }
#pragma unroll
        for (int j = 0; j < 8; j++) {
            s[j][0] = __expf(s[j][0] - m_r[0]);
            s[j][1] = __expf(s[j][1] - m_r[0]);
            s[j][2] = __expf(s[j][2] - m_r[1]);
            s[j][3] = __expf(s[j][3] - m_r[1]);
            psum[0] += s[j][0] + s[j][1];
            psum[1] += s[j][2] + s[j][3];
            acc_o[j][0] *= alpha[0]; acc_o[j][1] *= alpha[0];
            acc_o[j][2] *= alpha[1]; acc_o[j][3] *= alpha[1];
        }
#pragma unroll
        for (int off = 1; off < 4; off <<= 1) {
            psum[0] += __shfl_xor_sync(0xffffffffu, psum[0], off);
            psum[1] += __shfl_xor_sync(0xffffffffu, psum[1], off);
        }
        l_r[0] += psum[0];
        l_r[1] += psum[1];

        // ---- P fragments: C-layout -> A-layout, fp16 hi/lo split ----
        uint32_t aph[4][4], apl[4][4];
#pragma unroll
        for (int kk = 0; kk < 4; kk++) {
            const int j0 = 2 * kk, j1 = 2 * kk + 1;
            __half h0, h1, l0, l1;
            split_h(s[j0][0], h0, l0); split_h(s[j0][1], h1, l1);
            aph[kk][0] = pack_h2(h0, h1); apl[kk][0] = pack_h2(l0, l1);
            split_h(s[j0][2], h0, l0); split_h(s[j0][3], h1, l1);
            aph[kk][1] = pack_h2(h0, h1); apl[kk][1] = pack_h2(l0, l1);
            split_h(s[j1][0], h0, l0); split_h(s[j1][1], h1, l1);
            aph[kk][2] = pack_h2(h0, h1); apl[kk][2] = pack_h2(l0, l1);
            split_h(s[j1][2], h0, l0); split_h(s[j1][3], h1, l1);
            aph[kk][3] = pack_h2(h0, h1); apl[kk][3] = pack_h2(l0, l1);
        }

        // ---- O += P V  (2-term; V via ldmatrix.trans from [k][d]) ----
#pragma unroll
        for (int kk = 0; kk < 4; kk++) {
            const uint32_t vrow = sb + VSH_B +
                (uint32_t)((kk * 16 + (lane & 15)) * (APH * 2));
#pragma unroll
            for (int p2 = 0; p2 < 4; p2++) {
                uint32_t t0, t1, t2, t3;
                ldsm_x4_t(t0, t1, t2, t3, vrow + p2 * 32 + (lane >> 4) * 16);
                uint32_t bv0[2]; bv0[0] = t0; bv0[1] = t1;
                uint32_t bv1[2]; bv1[0] = t2; bv1[1] = t3;
                mma_f16(acc_o[2*p2],   aph[kk], bv0);
                mma_f16(acc_o[2*p2+1], aph[kk], bv1);
                mma_f16(acc_o[2*p2],   apl[kk], bv0);
                mma_f16(acc_o[2*p2+1], apl[kk], bv1);
            }
        }
    }

    // ---- epilogue: normalize, store fp16 to g_a [S][H*D] ----
    const float inv0 = 1.0f / l_r[0];
    const float inv1 = 1.0f / l_r[1];
    const int colb = h * HD + (lane & 3) * 2;
#pragma unroll
    for (int j2 = 0; j2 < 8; j2++) {
        const int col = colb + j2 * 8;
        __half2 v0 = __halves2half2(__float2half_rn(acc_o[j2][0] * inv0),
                                    __float2half_rn(acc_o[j2][1] * inv0));
        __half2 v1 = __halves2half2(__float2half_rn(acc_o[j2][2] * inv1),
                                    __float2half_rn(acc_o[j2][3] * inv1));
        *reinterpret_cast<__half2*>(g_a + (size_t)r0 * DIM + col)       = v0;
        *reinterpret_cast<__half2*>(g_a + (size_t)(r0 + 8) * DIM + col) = v1;
    }
}

// ---------------------------------------------------------------------------
// Launcher
// ---------------------------------------------------------------------------
extern "C" void kernel_launch(void* const* d_in, const int* in_sizes, int n_in,
                              void* d_out, int out_size)
{
    const float* x     = (const float*)d_in[0];   // [1,4096,1024]
    const float* w_qkv = (const float*)d_in[1];   // [1024,3072]
    const float* w_out = (const float*)d_in[2];   // [1024,1024]
    float* out = (float*)d_out;                   // [1,4096,1024]

    // Pre-pass: round x to fp16; transpose+round weights to fp16
    conv_x_kernel<<<SEQ * DIM / 4 / 256, 256>>>(x);
    tconv_wq_kernel<<<dim3(NQKV / 32, DIM / 32), dim3(32, 8)>>>(w_qkv);
    tconv_wo_kernel<<<dim3(DIM / 32, DIM / 32), dim3(32, 8)>>>(w_out);

    // 1) QKV projection (HMMA fp16, scatter into g_Q/g_K/g_V)
    cudaFuncSetAttribute(gemm_mma_kernel, cudaFuncAttributeMaxDynamicSharedMemorySize, GEMM_SMEM);
    gemm_mma_kernel<<<dim3(NQKV / 128, SEQ / 128), 128, GEMM_SMEM>>>(nullptr, 0);

    // 2) Sparse attention (HMMA, writes fp16 attn output)
    cudaFuncSetAttribute(attn_kernel, cudaFuncAttributeMaxDynamicSharedMemorySize, ATTN_SMEM);
    attn_kernel<<<dim3(SEQ / 64, NH), 128, ATTN_SMEM>>>();

    // 3) Output projection (HMMA fp16)
    gemm_mma_kernel<<<dim3(DIM / 128, SEQ / 128), 128, GEMM_SMEM>>>(out, 1);
}